// round 4
// baseline (speedup 1.0000x reference)
#include <cuda_runtime.h>

#define IMG 224
#define CS 8
#define NBINS 8
#define HC 28                      // cells per dim
#define FEAT (HC * HC * NBINS)     // 6272 per image
#define SROWS 32                   // pixel rows per strip
#define NSTRIPS (IMG / SROWS)      // 7
#define LROWS (SROWS + 2)          // 34 gray rows incl vertical halo
#define SSTRIDE 232                // smem row stride (floats)
#define NTH 224                    // one thread per column
#define ROW4 (IMG / 4)             // 56 float4 per image row

__device__ float g_partial[4096];  // per (image, strip) sum of squares

// bin = floor(mod(atan2(gy,gx), 2pi) / (pi/4)); branchless select tree
__device__ __forceinline__ int octant_bin(float gx, float gy) {
    int binP = (gx > 0.0f) ? ((gy < gx) ? 0 : 1) : ((gy > -gx) ? 2 : 3);
    int binN = (gx < 0.0f) ? ((-gy < -gx) ? 4 : 5) : ((gx < -gy) ? 6 : 7);
    int binZ = (gx >= 0.0f) ? 0 : 4;
    return (gy > 0.0f) ? binP : ((gy < 0.0f) ? binN : binZ);
}

__global__ void __launch_bounds__(NTH)
hog_kernel(const float* __restrict__ x,
           const float* __restrict__ gauss,
           float* __restrict__ out) {
    const int s   = blockIdx.x;     // strip
    const int b   = blockIdx.y;     // image
    const int tid = threadIdx.x;
    const int lane = tid & 31;
    const int warp = tid >> 5;

    __shared__ float sgray[LROWS * SSTRIDE];
    __shared__ float sg[CS * CS];
    __shared__ float wsum[NTH / 32];

    if (tid < CS * CS) sg[tid] = gauss[tid];
    // Zero side padding: only cols 3 and 228 of each row are ever read as halo
    if (tid < LROWS) {
        sgray[tid * SSTRIDE + 3]   = 0.0f;
        sgray[tid * SSTRIDE + 228] = 0.0f;
    }

    // Gray fill: 224 threads = 4 rows x 56 float4 per iteration, 8.5 iters
    const float* xb  = x + (size_t)b * 3 * IMG * IMG;
    const int    gr0 = s * SROWS - 1;
    {
        const int r0 = tid / ROW4;       // 0..3
        const int q  = tid - r0 * ROW4;  // 0..55
        for (int rr = r0; rr < LROWS; rr += 4) {
            const int gr = gr0 + rr;
            float4 o = make_float4(0.f, 0.f, 0.f, 0.f);
            if (gr >= 0 && gr < IMG) {
                const float* base = xb + gr * IMG + q * 4;
                float4 r4 = *(const float4*)(base);
                float4 g4 = *(const float4*)(base + IMG * IMG);
                float4 b4 = *(const float4*)(base + 2 * IMG * IMG);
                o.x = fmaf(0.2989f, r4.x, fmaf(0.587f, g4.x, 0.114f * b4.x));
                o.y = fmaf(0.2989f, r4.y, fmaf(0.587f, g4.y, 0.114f * b4.y));
                o.z = fmaf(0.2989f, r4.z, fmaf(0.587f, g4.z, 0.114f * b4.z));
                o.w = fmaf(0.2989f, r4.w, fmaf(0.587f, g4.w, 0.114f * b4.w));
            }
            *(float4*)(sgray + rr * SSTRIDE + 4 + q * 4) = o;
        }
    }
    __syncthreads();

    // One thread per column: separable Sobel with rolling rows.
    // t[r] = g[r][c-1] + 2g[r][c] + g[r][c+1]   -> gy = t[r+1] - t[r-1]
    // d[r] = g[r][c+1] - g[r][c-1]              -> gx = d[r-1] + 2d[r] + d[r+1]
    const float* col = sgray + tid + 4;

    float gwv[8];
#pragma unroll
    for (int p = 0; p < 8; p++) gwv[p] = sg[p * CS + (tid & 7)];

    float t0, t1, d0, d1;
    {
        float a = col[-1], m = col[0], z = col[1];
        t0 = a + 2.0f * m + z;  d0 = z - a;
        a = col[SSTRIDE - 1]; m = col[SSTRIDE]; z = col[SSTRIDE + 1];
        t1 = a + 2.0f * m + z;  d1 = z - a;
    }

    float ssq = 0.0f;
    float* ob = out + (size_t)b * FEAT + s * 4 * 224;

#pragma unroll
    for (int half = 0; half < 4; half++) {
        float h[NBINS];
#pragma unroll
        for (int k = 0; k < NBINS; k++) h[k] = 0.0f;

#pragma unroll
        for (int p = 0; p < 8; p++) {
            const int rr = half * 8 + p + 2;
            float a = col[rr * SSTRIDE - 1];
            float m = col[rr * SSTRIDE];
            float z = col[rr * SSTRIDE + 1];
            float t2 = a + 2.0f * m + z;
            float d2 = z - a;

            float gx = fmaf(2.0f, d1, d0) + d2;
            float gy = t2 - t0;

            float s2 = fmaf(gy, gy, fmaf(gx, gx, 1e-6f));
            float mag;
            asm("sqrt.approx.f32 %0, %1;" : "=f"(mag) : "f"(s2));
            float w = mag * gwv[p];

            int bin = octant_bin(gx, gy);
#pragma unroll
            for (int k = 0; k < NBINS; k++)
                if (bin == k) h[k] += w;

            t0 = t1; t1 = t2; d0 = d1; d1 = d2;
        }

        // 8-lane multi-bin fold: within each 8-lane cell group, lane ends with bin = lane&7
        const bool q4 = (lane & 4) != 0;
        float s0 = q4 ? h[0] : h[4];
        float s1 = q4 ? h[1] : h[5];
        float s2_ = q4 ? h[2] : h[6];
        float s3 = q4 ? h[3] : h[7];
        float a0 = (q4 ? h[4] : h[0]) + __shfl_xor_sync(0xffffffffu, s0, 4);
        float a1 = (q4 ? h[5] : h[1]) + __shfl_xor_sync(0xffffffffu, s1, 4);
        float a2 = (q4 ? h[6] : h[2]) + __shfl_xor_sync(0xffffffffu, s2_, 4);
        float a3 = (q4 ? h[7] : h[3]) + __shfl_xor_sync(0xffffffffu, s3, 4);

        const bool q2 = (lane & 2) != 0;
        float u0 = q2 ? a0 : a2;
        float u1 = q2 ? a1 : a3;
        float c0 = (q2 ? a2 : a0) + __shfl_xor_sync(0xffffffffu, u0, 2);
        float c1 = (q2 ? a3 : a1) + __shfl_xor_sync(0xffffffffu, u1, 2);

        const bool q1 = (lane & 1) != 0;
        float v_ = q1 ? c0 : c1;
        float dsum = (q1 ? c1 : c0) + __shfl_xor_sync(0xffffffffu, v_, 1);

        // Coalesced: out[b][ (s*4+half)*28 + tid/8 ][ tid&7 ]
        ob[half * 224 + tid] = dsum;
        ssq = fmaf(dsum, dsum, ssq);
    }

    // Block sum of squares -> deterministic per-strip partial
#pragma unroll
    for (int o = 16; o > 0; o >>= 1)
        ssq += __shfl_xor_sync(0xffffffffu, ssq, o);
    if (lane == 0) wsum[warp] = ssq;
    __syncthreads();
    if (tid == 0) {
        float t = 0.0f;
#pragma unroll
        for (int w = 0; w < NTH / 32; w++) t += wsum[w];
        g_partial[b * NSTRIPS + s] = t;
    }
}

#define CHUNKS 4
#define C4 (FEAT / 4 / CHUNKS)     // 392 float4 per chunk

__global__ void __launch_bounds__(256)
scale_kernel(float* __restrict__ out) {
    const int chunk = blockIdx.x;
    const int b     = blockIdx.y;
    const int tid   = threadIdx.x;
    __shared__ float sinv;
    if (tid < 32) {
        float v = (tid < NSTRIPS) ? g_partial[b * NSTRIPS + tid] : 0.0f;
#pragma unroll
        for (int o = 4; o > 0; o >>= 1) v += __shfl_xor_sync(0xffffffffu, v, o);
        if (tid == 0) sinv = 1.0f / (sqrtf(v) + 1e-6f);
    }
    __syncthreads();
    const float inv = sinv;
    float4* o4 = (float4*)(out + (size_t)b * FEAT) + chunk * C4;
#pragma unroll
    for (int i = tid; i < C4; i += 256) {
        float4 v = o4[i];
        v.x *= inv; v.y *= inv; v.z *= inv; v.w *= inv;
        o4[i] = v;
    }
}

extern "C" void kernel_launch(void* const* d_in, const int* in_sizes, int n_in,
                              void* d_out, int out_size) {
    const float* x     = (const float*)d_in[0];
    const float* gauss = (const float*)d_in[1];
    float* out = (float*)d_out;

    const int bs = in_sizes[0] / (3 * IMG * IMG);

    dim3 grid(NSTRIPS, bs);
    hog_kernel<<<grid, NTH>>>(x, gauss, out);
    dim3 sgrid(CHUNKS, bs);
    scale_kernel<<<sgrid, 256>>>(out);
}

// round 5
// speedup vs baseline: 1.0050x; 1.0050x over previous
#include <cuda_runtime.h>

#define IMG 224
#define CS 8
#define NBINS 8
#define HC 28                      // cells per dim
#define FEAT (HC * HC * NBINS)     // 6272 per image
#define SROWS 32                   // pixel rows per strip
#define NSTRIPS (IMG / SROWS)      // 7
#define LROWS (SROWS + 2)          // 34 gray rows incl vertical halo
#define SSTRIDE 232                // smem row stride (floats)
#define NTH 224                    // one thread per column
#define ROW4 (IMG / 4)             // 56 float4 per image row
#define MAXB 1024

__device__ float        g_partial[MAXB * NSTRIPS];  // per (image, strip) sum of squares
__device__ unsigned int g_count[MAXB];              // zero-init; restored to 0 every call

// bin = floor(mod(atan2(gy,gx), 2pi) / (pi/4)); branchless select tree
__device__ __forceinline__ int octant_bin(float gx, float gy) {
    int binP = (gx > 0.0f) ? ((gy < gx) ? 0 : 1) : ((gy > -gx) ? 2 : 3);
    int binN = (gx < 0.0f) ? ((-gy < -gx) ? 4 : 5) : ((gx < -gy) ? 6 : 7);
    int binZ = (gx >= 0.0f) ? 0 : 4;
    return (gy > 0.0f) ? binP : ((gy < 0.0f) ? binN : binZ);
}

__global__ void __launch_bounds__(NTH)
hog_kernel(const float* __restrict__ x,
           const float* __restrict__ gauss,
           float* __restrict__ out) {
    const int s   = blockIdx.x;     // strip
    const int b   = blockIdx.y;     // image
    const int tid = threadIdx.x;
    const int lane = tid & 31;
    const int warp = tid >> 5;

    __shared__ float sgray[LROWS * SSTRIDE];
    __shared__ float sg[CS * CS];
    __shared__ float wsum[NTH / 32];
    __shared__ unsigned int s_arrive;
    __shared__ float s_inv;

    if (tid < CS * CS) sg[tid] = gauss[tid];
    // Zero side padding: only cols 3 and 228 of each row are ever read as halo
    if (tid < LROWS) {
        sgray[tid * SSTRIDE + 3]   = 0.0f;
        sgray[tid * SSTRIDE + 228] = 0.0f;
    }

    // Gray fill: 224 threads = 4 rows x 56 float4 per iteration
    const float* xb  = x + (size_t)b * 3 * IMG * IMG;
    const int    gr0 = s * SROWS - 1;
    {
        const int r0 = tid / ROW4;       // 0..3
        const int q  = tid - r0 * ROW4;  // 0..55
        for (int rr = r0; rr < LROWS; rr += 4) {
            const int gr = gr0 + rr;
            float4 o = make_float4(0.f, 0.f, 0.f, 0.f);
            if (gr >= 0 && gr < IMG) {
                const float* base = xb + gr * IMG + q * 4;
                float4 r4 = *(const float4*)(base);
                float4 g4 = *(const float4*)(base + IMG * IMG);
                float4 b4 = *(const float4*)(base + 2 * IMG * IMG);
                o.x = fmaf(0.2989f, r4.x, fmaf(0.587f, g4.x, 0.114f * b4.x));
                o.y = fmaf(0.2989f, r4.y, fmaf(0.587f, g4.y, 0.114f * b4.y));
                o.z = fmaf(0.2989f, r4.z, fmaf(0.587f, g4.z, 0.114f * b4.z));
                o.w = fmaf(0.2989f, r4.w, fmaf(0.587f, g4.w, 0.114f * b4.w));
            }
            *(float4*)(sgray + rr * SSTRIDE + 4 + q * 4) = o;
        }
    }
    __syncthreads();

    // One thread per column: separable Sobel with rolling rows.
    // t[r] = g[r][c-1] + 2g[r][c] + g[r][c+1]   -> gy = t[r+1] - t[r-1]
    // d[r] = g[r][c+1] - g[r][c-1]              -> gx = d[r-1] + 2d[r] + d[r+1]
    const float* col = sgray + tid + 4;

    float gwv[8];
#pragma unroll
    for (int p = 0; p < 8; p++) gwv[p] = sg[p * CS + (tid & 7)];

    float t0, t1, d0, d1;
    {
        float a = col[-1], m = col[0], z = col[1];
        t0 = a + 2.0f * m + z;  d0 = z - a;
        a = col[SSTRIDE - 1]; m = col[SSTRIDE]; z = col[SSTRIDE + 1];
        t1 = a + 2.0f * m + z;  d1 = z - a;
    }

    float ssq = 0.0f;
    float* ob = out + (size_t)b * FEAT + s * 4 * 224;

#pragma unroll
    for (int half = 0; half < 4; half++) {
        float h[NBINS];
#pragma unroll
        for (int k = 0; k < NBINS; k++) h[k] = 0.0f;

#pragma unroll
        for (int p = 0; p < 8; p++) {
            const int rr = half * 8 + p + 2;
            float a = col[rr * SSTRIDE - 1];
            float m = col[rr * SSTRIDE];
            float z = col[rr * SSTRIDE + 1];
            float t2 = a + 2.0f * m + z;
            float d2 = z - a;

            float gx = fmaf(2.0f, d1, d0) + d2;
            float gy = t2 - t0;

            float s2 = fmaf(gy, gy, fmaf(gx, gx, 1e-6f));
            float mag;
            asm("sqrt.approx.f32 %0, %1;" : "=f"(mag) : "f"(s2));
            float w = mag * gwv[p];

            int bin = octant_bin(gx, gy);
#pragma unroll
            for (int k = 0; k < NBINS; k++)
                if (bin == k) h[k] += w;

            t0 = t1; t1 = t2; d0 = d1; d1 = d2;
        }

        // 8-lane multi-bin fold: within each 8-lane cell group, lane ends with bin = lane&7
        const bool q4 = (lane & 4) != 0;
        float s0 = q4 ? h[0] : h[4];
        float s1 = q4 ? h[1] : h[5];
        float s2_ = q4 ? h[2] : h[6];
        float s3 = q4 ? h[3] : h[7];
        float a0 = (q4 ? h[4] : h[0]) + __shfl_xor_sync(0xffffffffu, s0, 4);
        float a1 = (q4 ? h[5] : h[1]) + __shfl_xor_sync(0xffffffffu, s1, 4);
        float a2 = (q4 ? h[6] : h[2]) + __shfl_xor_sync(0xffffffffu, s2_, 4);
        float a3 = (q4 ? h[7] : h[3]) + __shfl_xor_sync(0xffffffffu, s3, 4);

        const bool q2 = (lane & 2) != 0;
        float u0 = q2 ? a0 : a2;
        float u1 = q2 ? a1 : a3;
        float c0 = (q2 ? a2 : a0) + __shfl_xor_sync(0xffffffffu, u0, 2);
        float c1 = (q2 ? a3 : a1) + __shfl_xor_sync(0xffffffffu, u1, 2);

        const bool q1 = (lane & 1) != 0;
        float v_ = q1 ? c0 : c1;
        float dsum = (q1 ? c1 : c0) + __shfl_xor_sync(0xffffffffu, v_, 1);

        // Coalesced: out[b][ (s*4+half)*28 + tid/8 ][ tid&7 ]
        ob[half * 224 + tid] = dsum;
        ssq = fmaf(dsum, dsum, ssq);
    }

    // Block sum of squares -> deterministic per-strip partial
#pragma unroll
    for (int o = 16; o > 0; o >>= 1)
        ssq += __shfl_xor_sync(0xffffffffu, ssq, o);
    if (lane == 0) wsum[warp] = ssq;
    __syncthreads();
    if (tid == 0) {
        float t = 0.0f;
#pragma unroll
        for (int w = 0; w < NTH / 32; w++) t += wsum[w];
        g_partial[b * NSTRIPS + s] = t;
    }

    // ---- Fused normalization: last arriving block for image b scales it ----
    __threadfence();                       // publish out rows + g_partial
    if (tid == 0) s_arrive = atomicAdd(&g_count[b], 1u);
    __syncthreads();
    if (s_arrive == NSTRIPS - 1) {
        __threadfence();                   // acquire other strips' writes
        if (tid == 0) {
            float t = 0.0f;
#pragma unroll
            for (int i = 0; i < NSTRIPS; i++) t += g_partial[b * NSTRIPS + i];
            s_inv = 1.0f / (sqrtf(t) + 1e-6f);
            g_count[b] = 0;                // restore for next launch / replay
        }
        __syncthreads();
        const float inv = s_inv;
        float4* o4 = (float4*)(out + (size_t)b * FEAT);
#pragma unroll
        for (int i = 0; i < FEAT / 4 / NTH; i++) {   // 7 iterations
            float4 v = o4[i * NTH + tid];
            v.x *= inv; v.y *= inv; v.z *= inv; v.w *= inv;
            o4[i * NTH + tid] = v;
        }
    }
}

extern "C" void kernel_launch(void* const* d_in, const int* in_sizes, int n_in,
                              void* d_out, int out_size) {
    const float* x     = (const float*)d_in[0];
    const float* gauss = (const float*)d_in[1];
    float* out = (float*)d_out;

    const int bs = in_sizes[0] / (3 * IMG * IMG);

    dim3 grid(NSTRIPS, bs);
    hog_kernel<<<grid, NTH>>>(x, gauss, out);
}

// round 6
// speedup vs baseline: 1.2087x; 1.2027x over previous
#include <cuda_runtime.h>

#define IMG 224
#define CS 8
#define NBINS 8
#define HC 28                      // cells per dim
#define FEAT (HC * HC * NBINS)     // 6272 per image
#define SROWS 16                   // pixel rows per strip
#define NSTRIPS (IMG / SROWS)      // 14
#define LROWS (SROWS + 2)          // 18 gray rows incl vertical halo
#define SSTRIDE 232                // smem row stride (floats)
#define NTH 224                    // one thread per column
#define ROW4 (IMG / 4)             // 56 float4 per image row
#define MAXB 1024

__device__ float        g_partial[MAXB * NSTRIPS];  // per (image, strip) sum of squares
__device__ unsigned int g_count[MAXB];              // zero-init; restored to 0 every call

__global__ void __launch_bounds__(NTH)
hog_kernel(const float* __restrict__ x,
           const float* __restrict__ gauss,
           float* __restrict__ out) {
    const int s   = blockIdx.x;     // strip
    const int b   = blockIdx.y;     // image
    const int tid = threadIdx.x;
    const int lane = tid & 31;
    const int warp = tid >> 5;

    __shared__ float sgray[LROWS * SSTRIDE];
    __shared__ float sg[CS * CS];
    __shared__ float wsum[NTH / 32];
    __shared__ unsigned int s_arrive;
    __shared__ float s_inv;

    if (tid < CS * CS) sg[tid] = gauss[tid];
    // Zero side padding: only cols 3 and 228 of each row are ever read as halo
    if (tid < LROWS) {
        sgray[tid * SSTRIDE + 3]   = 0.0f;
        sgray[tid * SSTRIDE + 228] = 0.0f;
    }

    // Gray fill: 224 threads = 4 rows x 56 float4 per iteration
    const float* xb  = x + (size_t)b * 3 * IMG * IMG;
    const int    gr0 = s * SROWS - 1;
    {
        const int r0 = tid / ROW4;       // 0..3
        const int q  = tid - r0 * ROW4;  // 0..55
        for (int rr = r0; rr < LROWS; rr += 4) {
            const int gr = gr0 + rr;
            float4 o = make_float4(0.f, 0.f, 0.f, 0.f);
            if (gr >= 0 && gr < IMG) {
                const float* base = xb + gr * IMG + q * 4;
                float4 r4 = *(const float4*)(base);
                float4 g4 = *(const float4*)(base + IMG * IMG);
                float4 b4 = *(const float4*)(base + 2 * IMG * IMG);
                o.x = fmaf(0.2989f, r4.x, fmaf(0.587f, g4.x, 0.114f * b4.x));
                o.y = fmaf(0.2989f, r4.y, fmaf(0.587f, g4.y, 0.114f * b4.y));
                o.z = fmaf(0.2989f, r4.z, fmaf(0.587f, g4.z, 0.114f * b4.z));
                o.w = fmaf(0.2989f, r4.w, fmaf(0.587f, g4.w, 0.114f * b4.w));
            }
            *(float4*)(sgray + rr * SSTRIDE + 4 + q * 4) = o;
        }
    }
    __syncthreads();

    // One thread per column: separable Sobel with rolling rows.
    // t[r] = g[r][c-1] + 2g[r][c] + g[r][c+1]   -> gy = t[r+1] - t[r-1]
    // d[r] = g[r][c+1] - g[r][c-1]              -> gx = d[r-1] + 2d[r] + d[r+1]
    const float* col = sgray + tid + 4;

    float gwv[8];
#pragma unroll
    for (int p = 0; p < 8; p++) gwv[p] = sg[p * CS + (tid & 7)];

    float t0, t1, d0, d1;
    {
        float a = col[-1], m = col[0], z = col[1];
        t0 = fmaf(2.0f, m, a + z);  d0 = z - a;
        a = col[SSTRIDE - 1]; m = col[SSTRIDE]; z = col[SSTRIDE + 1];
        t1 = fmaf(2.0f, m, a + z);  d1 = z - a;
    }

    float ssq = 0.0f;
    float* ob = out + (size_t)b * FEAT + s * 2 * 224;

#pragma unroll
    for (int half = 0; half < 2; half++) {
        // Quadrant-fold histogram: hs[j] = sum of w in class j (both signs),
        // hd[j] = signed sum (+w for gy>=0, -w for gy<0).
        float hs[4], hd[4];
#pragma unroll
        for (int k = 0; k < 4; k++) { hs[k] = 0.0f; hd[k] = 0.0f; }

#pragma unroll
        for (int p = 0; p < 8; p++) {
            const int rr = half * 8 + p + 2;
            float a = col[rr * SSTRIDE - 1];
            float m = col[rr * SSTRIDE];
            float z = col[rr * SSTRIDE + 1];
            float t2 = fmaf(2.0f, m, a + z);
            float d2 = z - a;

            float gx = fmaf(2.0f, d1, d0) + d2;
            float gy = t2 - t0;

            float s2 = fmaf(gy, gy, fmaf(gx, gx, 1e-6f));
            float mag;
            asm("sqrt.approx.f32 %0, %1;" : "=f"(mag) : "f"(s2));
            float w = mag * gwv[p];

            // class: on (gx2, |gy|) upper half-plane; sgn tracks which half gy was in
            const bool sn  = gy < 0.0f;
            float gx2 = sn ? -gx : gx;
            float sgn = sn ? -1.0f : 1.0f;
            float ay  = fabsf(gy);
            const bool pA = gx2 > 0.0f;
            const bool pD = ay < gx2;
            const bool pS = ay > -gx2;

            float w0 = (pA && pD)   ? w : 0.0f;
            float w1 = (pA && !pD)  ? w : 0.0f;
            float w2 = (!pA && pS)  ? w : 0.0f;
            float w3 = (!pA && !pS) ? w : 0.0f;
            hs[0] += w0;  hd[0] = fmaf(sgn, w0, hd[0]);
            hs[1] += w1;  hd[1] = fmaf(sgn, w1, hd[1]);
            hs[2] += w2;  hd[2] = fmaf(sgn, w2, hd[2]);
            hs[3] += w3;  hd[3] = fmaf(sgn, w3, hd[3]);

            t0 = t1; t1 = t2; d0 = d1; d1 = d2;
        }

        // Reconstruct 8 bins: bin j = class j with gy>=0, bin j+4 = class j with gy<0
        float h[NBINS];
#pragma unroll
        for (int k = 0; k < 4; k++) {
            float e = 0.5f * hs[k];
            h[k]     = fmaf( 0.5f, hd[k], e);
            h[k + 4] = fmaf(-0.5f, hd[k], e);
        }

        // 8-lane multi-bin fold: within each 8-lane cell group, lane ends with bin = lane&7
        const bool q4 = (lane & 4) != 0;
        float s0 = q4 ? h[0] : h[4];
        float s1 = q4 ? h[1] : h[5];
        float s2_ = q4 ? h[2] : h[6];
        float s3 = q4 ? h[3] : h[7];
        float a0 = (q4 ? h[4] : h[0]) + __shfl_xor_sync(0xffffffffu, s0, 4);
        float a1 = (q4 ? h[5] : h[1]) + __shfl_xor_sync(0xffffffffu, s1, 4);
        float a2 = (q4 ? h[6] : h[2]) + __shfl_xor_sync(0xffffffffu, s2_, 4);
        float a3 = (q4 ? h[7] : h[3]) + __shfl_xor_sync(0xffffffffu, s3, 4);

        const bool q2 = (lane & 2) != 0;
        float u0 = q2 ? a0 : a2;
        float u1 = q2 ? a1 : a3;
        float c0 = (q2 ? a2 : a0) + __shfl_xor_sync(0xffffffffu, u0, 2);
        float c1 = (q2 ? a3 : a1) + __shfl_xor_sync(0xffffffffu, u1, 2);

        const bool q1 = (lane & 1) != 0;
        float v_ = q1 ? c0 : c1;
        float dsum = (q1 ? c1 : c0) + __shfl_xor_sync(0xffffffffu, v_, 1);

        // Coalesced: out[b][ (s*2+half)*28 + tid/8 ][ tid&7 ]
        ob[half * 224 + tid] = dsum;
        ssq = fmaf(dsum, dsum, ssq);
    }

    // Block sum of squares -> deterministic per-strip partial
#pragma unroll
    for (int o = 16; o > 0; o >>= 1)
        ssq += __shfl_xor_sync(0xffffffffu, ssq, o);
    if (lane == 0) wsum[warp] = ssq;
    __syncthreads();
    if (tid == 0) {
        float t = 0.0f;
#pragma unroll
        for (int w = 0; w < NTH / 32; w++) t += wsum[w];
        g_partial[b * NSTRIPS + s] = t;
    }

    // ---- Fused normalization: last arriving block for image b scales it ----
    __threadfence();                       // publish out rows + g_partial
    if (tid == 0) s_arrive = atomicAdd(&g_count[b], 1u);
    __syncthreads();
    if (s_arrive == NSTRIPS - 1) {
        __threadfence();                   // acquire other strips' writes
        if (tid == 0) {
            float t = 0.0f;
#pragma unroll
            for (int i = 0; i < NSTRIPS; i++) t += g_partial[b * NSTRIPS + i];
            s_inv = 1.0f / (sqrtf(t) + 1e-6f);
            g_count[b] = 0;                // restore for next launch / replay
        }
        __syncthreads();
        const float inv = s_inv;
        float4* o4 = (float4*)(out + (size_t)b * FEAT);
#pragma unroll
        for (int i = 0; i < FEAT / 4 / NTH; i++) {   // 7 iterations
            float4 v = o4[i * NTH + tid];
            v.x *= inv; v.y *= inv; v.z *= inv; v.w *= inv;
            o4[i * NTH + tid] = v;
        }
    }
}

extern "C" void kernel_launch(void* const* d_in, const int* in_sizes, int n_in,
                              void* d_out, int out_size) {
    const float* x     = (const float*)d_in[0];
    const float* gauss = (const float*)d_in[1];
    float* out = (float*)d_out;

    const int bs = in_sizes[0] / (3 * IMG * IMG);

    dim3 grid(NSTRIPS, bs);
    hog_kernel<<<grid, NTH>>>(x, gauss, out);
}

// round 7
// speedup vs baseline: 1.2816x; 1.0603x over previous
#include <cuda_runtime.h>

#define IMG 224
#define CS 8
#define NBINS 8
#define HC 28                      // cells per dim
#define FEAT (HC * HC * NBINS)     // 6272 per image
#define SROWS 16                   // pixel rows per strip
#define NSTRIPS (IMG / SROWS)      // 14
#define LROWS (SROWS + 2)          // 18 gray rows incl vertical halo
#define SSTRIDE 232                // smem row stride (floats)
#define NTH 224                    // one thread per column
#define ROW4 (IMG / 4)             // 56 float4 per image row
#define MAXB 1024

// Gaussian (SIGMA=1, CS=8) is separable: g[p][c] = GY(p)*GX(c), coords p-3.5
#define GW3 0.0021874911f          // exp(-6.125)
#define GW2 0.0439369336f          // exp(-3.125)
#define GW1 0.3246524674f          // exp(-1.125)
#define GW0 0.8824969026f          // exp(-0.125)

__device__ float        g_partial[MAXB * NSTRIPS];  // per (image, strip) sum of squares
__device__ unsigned int g_count[MAXB];              // zero-init; restored to 0 every call

__constant__ float c_gy[8] = { GW3, GW2, GW1, GW0, GW0, GW1, GW2, GW3 };

__global__ void __launch_bounds__(NTH, 8)
hog_kernel(const float* __restrict__ x,
           float* __restrict__ out) {
    const int s   = blockIdx.x;     // strip
    const int b   = blockIdx.y;     // image
    const int tid = threadIdx.x;
    const int lane = tid & 31;
    const int warp = tid >> 5;

    __shared__ float sgray[LROWS * SSTRIDE];
    __shared__ float wsum[NTH / 32];
    __shared__ unsigned int s_arrive;
    __shared__ float s_inv;

    // Zero side padding: only cols 3 and 228 of each row are ever read as halo
    if (tid < LROWS) {
        sgray[tid * SSTRIDE + 3]   = 0.0f;
        sgray[tid * SSTRIDE + 228] = 0.0f;
    }

    // Gray fill: 224 threads = 4 rows x 56 float4 per iteration
    const float* xb  = x + (size_t)b * 3 * IMG * IMG;
    const int    gr0 = s * SROWS - 1;
    {
        const int r0 = tid / ROW4;       // 0..3
        const int q  = tid - r0 * ROW4;  // 0..55
        if (s != 0 && s != NSTRIPS - 1) {
            // interior strip: all rows in-bounds, unconditional loads
#pragma unroll
            for (int rr = r0; rr < LROWS; rr += 4) {
                const float* base = xb + (gr0 + rr) * IMG + q * 4;
                float4 r4 = *(const float4*)(base);
                float4 g4 = *(const float4*)(base + IMG * IMG);
                float4 b4 = *(const float4*)(base + 2 * IMG * IMG);
                float4 o;
                o.x = fmaf(0.2989f, r4.x, fmaf(0.587f, g4.x, 0.114f * b4.x));
                o.y = fmaf(0.2989f, r4.y, fmaf(0.587f, g4.y, 0.114f * b4.y));
                o.z = fmaf(0.2989f, r4.z, fmaf(0.587f, g4.z, 0.114f * b4.z));
                o.w = fmaf(0.2989f, r4.w, fmaf(0.587f, g4.w, 0.114f * b4.w));
                *(float4*)(sgray + rr * SSTRIDE + 4 + q * 4) = o;
            }
        } else {
#pragma unroll
            for (int rr = r0; rr < LROWS; rr += 4) {
                const int gr = gr0 + rr;
                float4 o = make_float4(0.f, 0.f, 0.f, 0.f);
                if (gr >= 0 && gr < IMG) {
                    const float* base = xb + gr * IMG + q * 4;
                    float4 r4 = *(const float4*)(base);
                    float4 g4 = *(const float4*)(base + IMG * IMG);
                    float4 b4 = *(const float4*)(base + 2 * IMG * IMG);
                    o.x = fmaf(0.2989f, r4.x, fmaf(0.587f, g4.x, 0.114f * b4.x));
                    o.y = fmaf(0.2989f, r4.y, fmaf(0.587f, g4.y, 0.114f * b4.y));
                    o.z = fmaf(0.2989f, r4.z, fmaf(0.587f, g4.z, 0.114f * b4.z));
                    o.w = fmaf(0.2989f, r4.w, fmaf(0.587f, g4.w, 0.114f * b4.w));
                }
                *(float4*)(sgray + rr * SSTRIDE + 4 + q * 4) = o;
            }
        }
    }
    __syncthreads();

    // One thread per column: separable Sobel with rolling rows.
    const float* col = sgray + tid + 4;

    // Column Gaussian factor (folded into reconstruct): hg = 0.5 * GX(tid&7)
    const int c7 = tid & 7;
    const int dc = min(c7, 7 - c7);    // 0..3, coord |c-3.5| = 3.5-dc
    const float gxc = (dc == 3) ? GW0 : (dc == 2) ? GW1 : (dc == 1) ? GW2 : GW3;
    const float hg = 0.5f * gxc;

    float t0, t1, d0, d1;
    {
        float a = col[-1], m = col[0], z = col[1];
        t0 = fmaf(2.0f, m, a + z);  d0 = z - a;
        a = col[SSTRIDE - 1]; m = col[SSTRIDE]; z = col[SSTRIDE + 1];
        t1 = fmaf(2.0f, m, a + z);  d1 = z - a;
    }

    float ssq = 0.0f;
    float* ob = out + (size_t)b * FEAT + s * 2 * 224;

#pragma unroll
    for (int half = 0; half < 2; half++) {
        // Quadrant-fold histogram: hs[j] = sum of w in class j (both gy signs),
        // hd[j] = signed sum (+w for gy>=0, -w for gy<0).
        float hs[4], hd[4];
#pragma unroll
        for (int k = 0; k < 4; k++) { hs[k] = 0.0f; hd[k] = 0.0f; }

#pragma unroll
        for (int p = 0; p < 8; p++) {
            const int rr = half * 8 + p + 2;
            float a = col[rr * SSTRIDE - 1];
            float m = col[rr * SSTRIDE];
            float z = col[rr * SSTRIDE + 1];
            float t2 = fmaf(2.0f, m, a + z);
            float d2 = z - a;

            float gx = fmaf(2.0f, d1, d0) + d2;
            float gy = t2 - t0;

            float s2 = fmaf(gy, gy, fmaf(gx, gx, 1e-6f));
            float mag;
            asm("sqrt.approx.f32 %0, %1;" : "=f"(mag) : "f"(s2));
            float w = mag * c_gy[p];   // p compile-time -> immediate multiplier

            // classify on (gx2, |gy|) upper half-plane; sn = which gy half
            const bool sn  = gy < 0.0f;
            float gx2 = sn ? -gx : gx;
            float sgn = sn ? -1.0f : 1.0f;
            float ay  = fabsf(gy);
            const bool pA = gx2 > 0.0f;
            const bool pD = ay < gx2;      // pD => pA
            const bool pS = ay > -gx2;     // pA => pS

            float w0 = pD         ? w : 0.0f;
            float w1 = (pA != pD) ? w : 0.0f;
            float w2 = (pA != pS) ? w : 0.0f;
            float w3 = !pS        ? w : 0.0f;
            hs[0] += w0;  hd[0] = fmaf(sgn, w0, hd[0]);
            hs[1] += w1;  hd[1] = fmaf(sgn, w1, hd[1]);
            hs[2] += w2;  hd[2] = fmaf(sgn, w2, hd[2]);
            hs[3] += w3;  hd[3] = fmaf(sgn, w3, hd[3]);

            t0 = t1; t1 = t2; d0 = d1; d1 = d2;
        }

        // Reconstruct 8 bins with column-Gaussian folded in:
        // h[k] = gxc*0.5*(hs+hd), h[k+4] = gxc*0.5*(hs-hd)
        float h[NBINS];
#pragma unroll
        for (int k = 0; k < 4; k++) {
            float e = hg * hs[k];
            h[k]     = fmaf( hg, hd[k], e);
            h[k + 4] = fmaf(-hg, hd[k], e);
        }

        // 8-lane multi-bin fold: within each 8-lane cell group, lane ends with bin = lane&7
        const bool q4 = (lane & 4) != 0;
        float s0 = q4 ? h[0] : h[4];
        float s1 = q4 ? h[1] : h[5];
        float s2_ = q4 ? h[2] : h[6];
        float s3 = q4 ? h[3] : h[7];
        float a0 = (q4 ? h[4] : h[0]) + __shfl_xor_sync(0xffffffffu, s0, 4);
        float a1 = (q4 ? h[5] : h[1]) + __shfl_xor_sync(0xffffffffu, s1, 4);
        float a2 = (q4 ? h[6] : h[2]) + __shfl_xor_sync(0xffffffffu, s2_, 4);
        float a3 = (q4 ? h[7] : h[3]) + __shfl_xor_sync(0xffffffffu, s3, 4);

        const bool q2 = (lane & 2) != 0;
        float u0 = q2 ? a0 : a2;
        float u1 = q2 ? a1 : a3;
        float c0 = (q2 ? a2 : a0) + __shfl_xor_sync(0xffffffffu, u0, 2);
        float c1 = (q2 ? a3 : a1) + __shfl_xor_sync(0xffffffffu, u1, 2);

        const bool q1 = (lane & 1) != 0;
        float v_ = q1 ? c0 : c1;
        float dsum = (q1 ? c1 : c0) + __shfl_xor_sync(0xffffffffu, v_, 1);

        // Coalesced: out[b][ (s*2+half)*28 + tid/8 ][ tid&7 ]
        ob[half * 224 + tid] = dsum;
        ssq = fmaf(dsum, dsum, ssq);
    }

    // Block sum of squares -> deterministic per-strip partial
#pragma unroll
    for (int o = 16; o > 0; o >>= 1)
        ssq += __shfl_xor_sync(0xffffffffu, ssq, o);
    if (lane == 0) wsum[warp] = ssq;
    __syncthreads();
    if (tid == 0) {
        float t = 0.0f;
#pragma unroll
        for (int w = 0; w < NTH / 32; w++) t += wsum[w];
        g_partial[b * NSTRIPS + s] = t;
    }

    // ---- Fused normalization: last arriving block for image b scales it ----
    __threadfence();                       // publish out rows + g_partial
    if (tid == 0) s_arrive = atomicAdd(&g_count[b], 1u);
    __syncthreads();
    if (s_arrive == NSTRIPS - 1) {
        __threadfence();                   // acquire other strips' writes
        if (tid == 0) {
            float t = 0.0f;
#pragma unroll
            for (int i = 0; i < NSTRIPS; i++) t += g_partial[b * NSTRIPS + i];
            s_inv = 1.0f / (sqrtf(t) + 1e-6f);
            g_count[b] = 0;                // restore for next launch / replay
        }
        __syncthreads();
        const float inv = s_inv;
        float4* o4 = (float4*)(out + (size_t)b * FEAT);
#pragma unroll
        for (int i = 0; i < FEAT / 4 / NTH; i++) {   // 7 iterations
            float4 v = o4[i * NTH + tid];
            v.x *= inv; v.y *= inv; v.z *= inv; v.w *= inv;
            o4[i * NTH + tid] = v;
        }
    }
}

extern "C" void kernel_launch(void* const* d_in, const int* in_sizes, int n_in,
                              void* d_out, int out_size) {
    const float* x = (const float*)d_in[0];
    float* out = (float*)d_out;

    const int bs = in_sizes[0] / (3 * IMG * IMG);

    dim3 grid(NSTRIPS, bs);
    hog_kernel<<<grid, NTH>>>(x, out);
}